// round 1
// baseline (speedup 1.0000x reference)
#include <cuda_runtime.h>
#include <cuda_bf16.h>
#include <cstdint>

#define Bq 8
#define Nn 2048
#define Dd 128
#define DE 136            // 128 emb + hsq + ones + 6 zero pad (multiple of 8)
#define TM 128
#define TK 64
#define TKP 68            // padded smem stride (bf16 units)
#define KSPLIT 4
#define NBLK (Bq * (Nn / TM) * KSPLIT)   // 512

// scratch (no allocation allowed -> device globals)
__device__ float          g_hsq[Bq * Nn];
__device__ __nv_bfloat16  g_HextT[(size_t)Bq * DE * Nn];   // [b][d][j]  (transposed)
__device__ float          g_part[NBLK];

// ---------------------------------------------------------------------------
// Kernel 0: squared norms per node (warp per row)
// ---------------------------------------------------------------------------
__global__ void k_hsq(const float* __restrict__ H) {
    int warp = (blockIdx.x * blockDim.x + threadIdx.x) >> 5;
    int lane = threadIdx.x & 31;
    if (warp >= Bq * Nn) return;
    float4 v = ((const float4*)(H + (size_t)warp * Dd))[lane];
    float s = v.x * v.x + v.y * v.y + v.z * v.z + v.w * v.w;
    #pragma unroll
    for (int o = 16; o; o >>= 1) s += __shfl_xor_sync(0xFFFFFFFFu, s, o);
    if (lane == 0) g_hsq[warp] = s;
}

// ---------------------------------------------------------------------------
// Kernel 1: build transposed extended embedding  HextT[b][d][j] (bf16)
//   d<128: H,  d=128: hsq,  d=129: 1,  d>=130: 0
// ---------------------------------------------------------------------------
__global__ void k_build(const float* __restrict__ H) {
    __shared__ __nv_bfloat16 s[DE][TKP];
    int b  = blockIdx.y;
    int j0 = blockIdx.x * TK;
    int tid = threadIdx.x;                       // 256 threads

    for (int idx = tid; idx < TK * Dd; idx += 256) {
        int jj = idx >> 7, d = idx & 127;        // coalesced over d
        float v = H[((size_t)b * Nn + j0 + jj) * Dd + d];
        s[d][jj] = __float2bfloat16(v);
    }
    if (tid < TK) {
        float hs = g_hsq[b * Nn + j0 + tid];
        s[128][tid] = __float2bfloat16(hs);
        s[129][tid] = __float2bfloat16(1.0f);
        #pragma unroll
        for (int d = 130; d < DE; d++) s[d][tid] = __float2bfloat16(0.0f);
    }
    __syncthreads();
    for (int idx = tid; idx < DE * TK; idx += 256) {
        int d = idx >> 6, jj = idx & 63;         // coalesced writes (128B rows)
        g_HextT[((size_t)b * DE + d) * Nn + j0 + jj] = s[d][jj];
    }
}

// ---------------------------------------------------------------------------
// Kernel 2: fused GEMM + epilogue.
// Block = 128 rows of A (one m-tile) x one K-split range. G tile (128x136)
// lives in mma accumulators; epilogue dots it with per-(i,d) weights and
// writes ONE partial float per block (deterministic).
// ---------------------------------------------------------------------------
__global__ __launch_bounds__(256, 2) void k_main(const float* __restrict__ A,
                                                 const float* __restrict__ H) {
    __shared__ __nv_bfloat16 sA[TM][TKP];   // 128 x 68
    __shared__ __nv_bfloat16 sB[DE][TKP];   // 136 x 68
    __shared__ float s_red[8];

    const int ks  = blockIdx.x;             // 0..KSPLIT-1
    const int mt  = blockIdx.y;             // 0..15
    const int b   = blockIdx.z;             // 0..7
    const int tid = threadIdx.x;
    const int lane = tid & 31, w = tid >> 5;
    const int i0 = mt * TM;
    const int k_beg = ks * (Nn / KSPLIT);
    const int k_end = k_beg + (Nn / KSPLIT);

    float acc[17][4];
    #pragma unroll
    for (int nt = 0; nt < 17; nt++)
        #pragma unroll
        for (int r = 0; r < 4; r++) acc[nt][r] = 0.f;

    const float* Ab = A + (size_t)b * Nn * Nn;
    const __nv_bfloat16* Hb = g_HextT + (size_t)b * DE * Nn;

    for (int k = k_beg; k < k_end; k += TK) {
        __syncthreads();
        // A tile: 128x64 fp32 -> bf16 in-register -> smem
        #pragma unroll
        for (int m = 0; m < 8; m++) {
            int idx = tid + m * 256;                    // 0..2047
            int row = idx >> 4, c4 = (idx & 15) << 2;   // float4 granularity
            float4 v = *(const float4*)(Ab + (size_t)(i0 + row) * Nn + k + c4);
            __nv_bfloat162 p0 = __floats2bfloat162_rn(v.x, v.y);
            __nv_bfloat162 p1 = __floats2bfloat162_rn(v.z, v.w);
            uint2 pk;
            pk.x = *reinterpret_cast<uint32_t*>(&p0);
            pk.y = *reinterpret_cast<uint32_t*>(&p1);
            *(uint2*)&sA[row][c4] = pk;
        }
        // B tile: HextT rows (d-major) 136 x 64 bf16, 8B chunks
        for (int idx = tid; idx < DE * 16; idx += 256) {
            int d = idx >> 4, c = (idx & 15) << 2;
            uint2 v = *(const uint2*)(Hb + (size_t)d * Nn + k + c);
            *(uint2*)&sB[d][c] = v;
        }
        __syncthreads();

        #pragma unroll
        for (int kk = 0; kk < 4; kk++) {
            const int k16 = kk * 16;
            const int r = w * 16 + (lane >> 2);
            const int q = (lane & 3) * 2;
            uint32_t a0 = *(uint32_t*)&sA[r][k16 + q];
            uint32_t a1 = *(uint32_t*)&sA[r + 8][k16 + q];
            uint32_t a2 = *(uint32_t*)&sA[r][k16 + q + 8];
            uint32_t a3 = *(uint32_t*)&sA[r + 8][k16 + q + 8];
            #pragma unroll
            for (int nt = 0; nt < 17; nt++) {
                const int col = nt * 8 + (lane >> 2);
                uint32_t b0 = *(uint32_t*)&sB[col][k16 + q];
                uint32_t b1 = *(uint32_t*)&sB[col][k16 + q + 8];
                asm volatile(
                    "mma.sync.aligned.m16n8k16.row.col.f32.bf16.bf16.f32 "
                    "{%0,%1,%2,%3}, {%4,%5,%6,%7}, {%8,%9}, {%0,%1,%2,%3};\n"
                    : "+f"(acc[nt][0]), "+f"(acc[nt][1]),
                      "+f"(acc[nt][2]), "+f"(acc[nt][3])
                    : "r"(a0), "r"(a1), "r"(a2), "r"(a3), "r"(b0), "r"(b1));
            }
        }
    }

    // Epilogue: weighted reduction of accumulator tile
    float tsum = 0.f;
    const int r_lo = i0 + w * 16 + (lane >> 2);
    const int dq = (lane & 3) * 2;
    #pragma unroll
    for (int nt = 0; nt < 17; nt++) {
        #pragma unroll
        for (int h = 0; h < 2; h++) {
            const int i = r_lo + h * 8;
            #pragma unroll
            for (int e = 0; e < 2; e++) {
                const int d = nt * 8 + dq + e;
                float c = acc[nt][h * 2 + e];
                float wgt;
                if (d < Dd)         wgt = -2.f * H[((size_t)b * Nn + i) * Dd + d];
                else if (d == 128)  wgt = 1.f;
                else if (d == 129)  wgt = g_hsq[b * Nn + i];
                else                wgt = 0.f;
                tsum += c * wgt;
            }
        }
    }
    #pragma unroll
    for (int o = 16; o; o >>= 1) tsum += __shfl_xor_sync(0xFFFFFFFFu, tsum, o);
    if (lane == 0) s_red[w] = tsum;
    __syncthreads();
    if (tid == 0) {
        float bs = 0.f;
        #pragma unroll
        for (int x = 0; x < 8; x++) bs += s_red[x];
        g_part[(b * (Nn / TM) + mt) * KSPLIT + ks] = bs;
    }
}

// ---------------------------------------------------------------------------
// Kernel 3: deterministic final reduction
// ---------------------------------------------------------------------------
__global__ void k_final(float* __restrict__ out) {
    __shared__ float s[NBLK];
    int t = threadIdx.x;
    s[t] = g_part[t];
    __syncthreads();
    #pragma unroll
    for (int o = NBLK / 2; o; o >>= 1) {
        if (t < o) s[t] += s[t + o];
        __syncthreads();
    }
    if (t == 0) out[0] = s[0] / (float)(Bq * Nn);
}

// ---------------------------------------------------------------------------
extern "C" void kernel_launch(void* const* d_in, const int* in_sizes, int n_in,
                              void* d_out, int out_size) {
    const float* adj = (const float*)d_in[0];
    const float* emb = (const float*)d_in[1];
    k_hsq<<<Bq * Nn / 8, 256>>>(emb);
    dim3 g1(Nn / TK, Bq);
    k_build<<<g1, 256>>>(emb);
    dim3 g2(KSPLIT, Nn / TM, Bq);
    k_main<<<g2, 256>>>(adj, emb);
    k_final<<<1, NBLK>>>((float*)d_out);
}

// round 3
// speedup vs baseline: 1.7941x; 1.7941x over previous
#include <cuda_runtime.h>
#include <cuda_bf16.h>
#include <cstdint>

#define Bq 8
#define Nn 2048
#define Dd 128
#define DE 144            // 128 emb + hsq + ones + 14 zero pad -> 18 n8-tiles
#define TM 128
#define TK 32             // K elements per pipeline stage
#define NS 3              // cp.async stages
#define KSPLIT 2
#define NTILE (DE / 8)    // 18
#define NBLK (Bq * (Nn / TM) * KSPLIT)   // 256

// smem layout (bytes); strides chosen for conflict-free LDS patterns
#define A_STRIDE 160      // 128B fp32 data + 32B pad  (stride ≡ 32 mod 128)
#define B_STRIDE 80       // 64B bf16 data + 16B pad
#define A_STAGE  (TM * A_STRIDE)          // 20480
#define B_STAGE  (DE * B_STRIDE)          // 11520
#define STAGE_BYTES (A_STAGE + B_STAGE)   // 32000
#define SMEM_BYTES  (NS * STAGE_BYTES)    // 96000

// scratch (no allocation allowed -> device globals)
__device__ float          g_hsq[Bq * Nn];
__device__ __nv_bfloat16  g_HextT[(size_t)Bq * DE * Nn];  // [b][d][j] bf16
__device__ float          g_part[NBLK];

__device__ __forceinline__ uint32_t smem_u32(const void* p) {
    uint32_t a;
    asm("{ .reg .u64 t; cvta.to.shared.u64 t, %1; cvt.u32.u64 %0, t; }"
        : "=r"(a) : "l"(p));
    return a;
}
__device__ __forceinline__ void cp16(uint32_t dst, const void* src) {
    asm volatile("cp.async.cg.shared.global [%0], [%1], 16;"
                 :: "r"(dst), "l"(src) : "memory");
}
__device__ __forceinline__ uint32_t packbf(float x, float y) {
    __nv_bfloat162 p = __floats2bfloat162_rn(x, y);
    return *reinterpret_cast<uint32_t*>(&p);
}

// ---------------------------------------------------------------------------
// Kernel 0 (fused prep): hsq + bf16 transposed extended embedding
//   HextT[b][d][j]:  d<128: H,  d=128: hsq_j,  d=129: 1,  d>=130: 0
// ---------------------------------------------------------------------------
__global__ void k_prep(const float* __restrict__ H) {
    __shared__ float s2[32][136];   // [j][d], stride 136 words (8 mod 32)
    __shared__ float hq[32];
    const int b = blockIdx.y, j0 = blockIdx.x * 32;
    const int tid = threadIdx.x;    // 256

    #pragma unroll
    for (int i = 0; i < 16; i++) {
        int idx = tid + i * 256;
        int j = idx >> 7, d = idx & 127;        // coalesced over d
        s2[j][d] = H[((size_t)(b * Nn + j0 + j)) * Dd + d];
    }
    __syncthreads();

    {   // hsq: warp w -> 4 rows, 8 lanes per row
        const int w = tid >> 5, l = tid & 31;
        const int j = w * 4 + (l >> 3), sub = l & 7;
        float sum = 0.f;
        #pragma unroll
        for (int m = 0; m < 16; m++) {
            float v = s2[j][sub + 8 * m];
            sum += v * v;
        }
        sum += __shfl_xor_sync(0xFFFFFFFFu, sum, 1);
        sum += __shfl_xor_sync(0xFFFFFFFFu, sum, 2);
        sum += __shfl_xor_sync(0xFFFFFFFFu, sum, 4);
        if (sub == 0) { hq[j] = sum; g_hsq[b * Nn + j0 + j] = sum; }
    }
    __syncthreads();

    for (int idx = tid; idx < DE * 32; idx += 256) {
        int d = idx >> 5, j = idx & 31;          // coalesced over j
        float v = (d < 128) ? s2[j][d]
                : (d == 128) ? hq[j]
                : (d == 129) ? 1.0f : 0.0f;
        g_HextT[((size_t)(b * DE + d)) * Nn + j0 + j] = __float2bfloat16(v);
    }
}

// ---------------------------------------------------------------------------
// Kernel 1: pipelined bf16 GEMM + fused weighted-reduction epilogue.
// Grid (KSPLIT, 16, 8).  Warp grid 4(m) x 2(n): warp tile m32 x n72.
// A: fp32 via cp.async -> smem -> LDS.64 + F2FP at fragment load.
// B: bf16 (pre-built) via cp.async.
// ---------------------------------------------------------------------------
__global__ __launch_bounds__(256, 2)
void k_main(const float* __restrict__ A, const float* __restrict__ H) {
    extern __shared__ char smem[];
    __shared__ float s_red[8];
    const uint32_t sb0 = smem_u32(smem);
    const int tid = threadIdx.x;
    const int wid = tid >> 5, lane = tid & 31;
    const int ks = blockIdx.x, mt = blockIdx.y, b = blockIdx.z;
    const int i0 = mt * TM;
    const int kbase = ks * (Nn / KSPLIT);
    const int NIT = (Nn / KSPLIT) / TK;         // 32

    const int wm = wid >> 1;          // 0..3  (m-offset 32*wm)
    const int wn = wid & 1;           // 0..1  (tiles 9*wn .. 9*wn+8)
    const int qr = lane >> 2;         // 0..7
    const int qc = (lane & 3) * 2;    // 0,2,4,6

    const float* Ag = A + ((size_t)b * Nn + i0) * Nn + kbase;
    const __nv_bfloat16* Bg = g_HextT + ((size_t)b * DE) * Nn + kbase;

    float acc[2][9][4];
    #pragma unroll
    for (int f = 0; f < 2; f++)
        #pragma unroll
        for (int t = 0; t < 9; t++)
            #pragma unroll
            for (int r = 0; r < 4; r++) acc[f][t][r] = 0.f;

    // ---- stage issue (all 256 threads) ----
    auto issue = [&](int s, int it) {
        uint32_t sa = sb0 + s * STAGE_BYTES;
        const float* ag = Ag + it * TK;
        #pragma unroll
        for (int c = 0; c < 4; c++) {
            int e = tid + c * 256;                 // 0..1023
            int row = e >> 3, ch = e & 7;
            cp16(sa + row * A_STRIDE + ch * 16, ag + (size_t)row * Nn + ch * 4);
        }
        uint32_t sbB = sa + A_STAGE;
        const __nv_bfloat16* bg = Bg + it * TK;
        #pragma unroll
        for (int c = 0; c < 3; c++) {
            int e = tid + c * 256;                 // need 576
            if (e < DE * 4) {
                int row = e >> 2, ch = e & 3;
                cp16(sbB + row * B_STRIDE + ch * 16, bg + (size_t)row * Nn + ch * 8);
            }
        }
    };

    // prologue
    #pragma unroll
    for (int p = 0; p < NS - 1; p++) {
        issue(p, p);
        asm volatile("cp.async.commit_group;" ::: "memory");
    }

    for (int it = 0; it < NIT; it++) {
        const int pre = it + NS - 1;
        if (pre < NIT) issue(pre % NS, pre);
        asm volatile("cp.async.commit_group;" ::: "memory");
        asm volatile("cp.async.wait_group %0;" :: "n"(NS - 1) : "memory");
        __syncthreads();

        const char* smA = smem + (it % NS) * STAGE_BYTES;
        const char* smB = smA + A_STAGE;

        #pragma unroll
        for (int k16 = 0; k16 < TK; k16 += 16) {
            uint32_t a[2][4];
            #pragma unroll
            for (int f = 0; f < 2; f++) {
                const char* ap = smA + (wm * 32 + f * 16 + qr) * A_STRIDE;
                float2 v00 = *(const float2*)(ap + (k16 + qc) * 4);
                float2 v10 = *(const float2*)(ap + 8 * A_STRIDE + (k16 + qc) * 4);
                float2 v01 = *(const float2*)(ap + (k16 + qc + 8) * 4);
                float2 v11 = *(const float2*)(ap + 8 * A_STRIDE + (k16 + qc + 8) * 4);
                a[f][0] = packbf(v00.x, v00.y);
                a[f][1] = packbf(v10.x, v10.y);
                a[f][2] = packbf(v01.x, v01.y);
                a[f][3] = packbf(v11.x, v11.y);
            }
            #pragma unroll
            for (int t = 0; t < 9; t++) {
                const int n = (wn * 9 + t) * 8 + qr;
                uint32_t b0 = *(const uint32_t*)(smB + n * B_STRIDE + (k16 + qc) * 2);
                uint32_t b1 = *(const uint32_t*)(smB + n * B_STRIDE + (k16 + qc + 8) * 2);
                #pragma unroll
                for (int f = 0; f < 2; f++) {
                    asm volatile(
                        "mma.sync.aligned.m16n8k16.row.col.f32.bf16.bf16.f32 "
                        "{%0,%1,%2,%3}, {%4,%5,%6,%7}, {%8,%9}, {%0,%1,%2,%3};\n"
                        : "+f"(acc[f][t][0]), "+f"(acc[f][t][1]),
                          "+f"(acc[f][t][2]), "+f"(acc[f][t][3])
                        : "r"(a[f][0]), "r"(a[f][1]), "r"(a[f][2]), "r"(a[f][3]),
                          "r"(b0), "r"(b1));
                }
            }
        }
        __syncthreads();
    }

    // ---- epilogue: weighted reduction ----
    float tsum = 0.f;
    #pragma unroll
    for (int f = 0; f < 2; f++) {
        #pragma unroll
        for (int rr = 0; rr < 2; rr++) {
            const int i = i0 + wm * 32 + f * 16 + qr + rr * 8;
            const float* Hrow = H + ((size_t)(b * Nn + i)) * Dd;
            const float hsq_i = g_hsq[b * Nn + i];
            #pragma unroll
            for (int t = 0; t < 9; t++) {
                const int d0 = (wn * 9 + t) * 8 + qc;
                float c0 = acc[f][t][rr * 2 + 0];
                float c1 = acc[f][t][rr * 2 + 1];
                float w0, w1;
                if (d0 < 128)       { w0 = -2.f * Hrow[d0]; w1 = -2.f * Hrow[d0 + 1]; }
                else if (d0 == 128) { w0 = 1.f;             w1 = hsq_i; }
                else                { w0 = 0.f;             w1 = 0.f; }
                tsum += c0 * w0 + c1 * w1;
            }
        }
    }
    #pragma unroll
    for (int o = 16; o; o >>= 1) tsum += __shfl_xor_sync(0xFFFFFFFFu, tsum, o);
    if (lane == 0) s_red[wid] = tsum;
    __syncthreads();
    if (tid == 0) {
        float bs = 0.f;
        #pragma unroll
        for (int x = 0; x < 8; x++) bs += s_red[x];
        g_part[(b * (Nn / TM) + mt) * KSPLIT + ks] = bs;
    }
}

// ---------------------------------------------------------------------------
// Kernel 2: deterministic final reduction
// ---------------------------------------------------------------------------
__global__ void k_final(float* __restrict__ out) {
    __shared__ float s[NBLK];
    int t = threadIdx.x;
    s[t] = g_part[t];
    __syncthreads();
    #pragma unroll
    for (int o = NBLK / 2; o; o >>= 1) {
        if (t < o) s[t] += s[t + o];
        __syncthreads();
    }
    if (t == 0) out[0] = s[0] / (float)(Bq * Nn);
}

// ---------------------------------------------------------------------------
extern "C" void kernel_launch(void* const* d_in, const int* in_sizes, int n_in,
                              void* d_out, int out_size) {
    const float* adj = (const float*)d_in[0];
    const float* emb = (const float*)d_in[1];

    static bool attr_done = false;
    if (!attr_done) {
        cudaFuncSetAttribute(k_main, cudaFuncAttributeMaxDynamicSharedMemorySize,
                             SMEM_BYTES);
        attr_done = true;
    }

    dim3 gp(Nn / 32, Bq);
    k_prep<<<gp, 256>>>(emb);
    dim3 gm(KSPLIT, Nn / TM, Bq);
    k_main<<<gm, 256, SMEM_BYTES>>>(adj, emb);
    k_final<<<1, NBLK>>>((float*)d_out);
}